// round 7
// baseline (speedup 1.0000x reference)
#include <cuda_runtime.h>
#include <cstdint>

#define BATCHN 4096
#define NI 784
#define WID 16000
#define NHID 4
#define NCLS 10
#define W64 (BATCHN / 64)        // 64 u64 words per neuron (64 batch bits each)
#define GROUP (WID / NCLS)       // 1600 neurons per class
#define NPB 32                   // neurons per layer block

// L2-resident working set; referenced ONLY from device code.
__device__ uint64_t g_xp[(size_t)NI * W64];             // 401 KB
__device__ uint64_t g_h[2][(size_t)WID * W64];          // 2 x 8.2 MB

// Bool-encoding mode (runtime-detected): 0=u8, 1=4-byte word, 2=2-byte half.
__device__ int g_mode;

static __device__ __forceinline__ uint64_t* bufptr(int s) {
    return s == 0 ? g_xp : g_h[s - 1];
}

static __device__ __forceinline__ uint32_t read_bool(const void* __restrict__ p,
                                                     size_t e, int mode) {
    if (mode == 1) return ((const uint32_t*)p)[e] != 0u;
    if (mode == 0) return ((const uint8_t*)p)[e] != 0u;
    return ((const uint16_t*)p)[e] != 0u;
}

static __device__ __forceinline__ int detect_mode(const uint32_t* __restrict__ x) {
    bool w32 = true, bf16 = true, u8 = true;
    for (int i = 0; i < 64; i++) {
        uint32_t w = x[i];
        if (!(w == 0u || w == 1u || w == 0x3F800000u)) w32 = false;
        uint32_t h0 = w & 0xFFFFu, h1 = w >> 16;
        if (!((h0 == 0u || h0 == 0x3F80u) && (h1 == 0u || h1 == 0x3F80u))) bf16 = false;
        if ((w & 0xFEFEFEFEu) != 0u) u8 = false;
    }
    return w32 ? 1 : (bf16 ? 2 : (u8 ? 0 : 1));
}

// ---------------------------------------------------------------------------
// pack_x_k: tiled transpose through shared memory; fully coalesced x reads.
// Thread 0 of each block also detects the bool mode (idempotent g_mode write)
// so downstream kernels see it after this kernel completes.
// ---------------------------------------------------------------------------
__global__ void pack_x_k(const void* __restrict__ x) {
    __shared__ uint8_t tile[64][65];
    __shared__ int s_mode;
    if (threadIdx.x == 0) {
        int m = detect_mode((const uint32_t*)x);
        s_mode = m;
        g_mode = m;              // same value from every block: race-free
    }
    __syncthreads();
    int mode = s_mode;
    int w = blockIdx.x;                 // 0..63
    int i0 = blockIdx.y * 64;           // input tile base
    int tx = threadIdx.x & 63;
    int ty = threadIdx.x >> 6;          // 0..3
#pragma unroll
    for (int r = 0; r < 16; r++) {
        int j = r * 4 + ty;             // sample within word
        int i = i0 + tx;
        uint8_t v = 0;
        if (i < NI) v = (uint8_t)read_bool(x, (size_t)(w * 64 + j) * NI + i, mode);
        tile[j][tx] = v;
    }
    __syncthreads();
    if (threadIdx.x < 64) {
        int i = i0 + (int)threadIdx.x;
        if (i < NI) {
            uint64_t acc = 0;
#pragma unroll
            for (int j = 0; j < 64; j++)
                acc |= (uint64_t)tile[j][threadIdx.x] << j;
            g_xp[(size_t)i * W64 + w] = acc;
        }
    }
}

// ---------------------------------------------------------------------------
// layer_k: block = 32 neurons. Cooperative smem stage of ia/ib/neg kills the
// idx->gather dependent chain; each thread then computes 2 neurons x 4 words
// (8 independent LDG.128 gathers, 4 STG.128). Grid exact: 500 x 256.
// ---------------------------------------------------------------------------
__global__ void __launch_bounds__(256) layer_k(int srcsel, int dstsel,
                        const int* __restrict__ ia, const int* __restrict__ ib,
                        const void* __restrict__ ng, size_t ng_off) {
    __shared__ int s_ia[NPB], s_ib[NPB];
    __shared__ uint64_t s_m[2][NPB];
    int nb = blockIdx.x * NPB;
    int t = threadIdx.x;
    int mode = g_mode;
    if (t < 2 * NPB) {                      // 64 threads: neg masks
        int n = t >> 1;
        uint32_t v = read_bool(ng, ng_off + 2 * (size_t)(nb + n) + (t & 1), mode);
        s_m[t & 1][n] = 0ULL - (uint64_t)v;
    } else if (t < 3 * NPB) {               // 32 threads: ia
        s_ia[t - 2 * NPB] = ia[nb + t - 2 * NPB];
    } else if (t < 4 * NPB) {               // 32 threads: ib
        s_ib[t - 3 * NPB] = ib[nb + t - 3 * NPB];
    }
    __syncthreads();

    const uint64_t* __restrict__ src = bufptr(srcsel);
    uint64_t* __restrict__ dst = bufptr(dstsel);

    int q = t & 15;          // word quad: words [4q, 4q+3] -> ull2 index 2q
    int p = t >> 4;          // neuron pair 0..15
    int n0 = 2 * p, n1 = 2 * p + 1;

    const ulonglong2* __restrict__ a0p =
        (const ulonglong2*)(src + (size_t)s_ia[n0] * W64) + 2 * q;
    const ulonglong2* __restrict__ b0p =
        (const ulonglong2*)(src + (size_t)s_ib[n0] * W64) + 2 * q;
    const ulonglong2* __restrict__ a1p =
        (const ulonglong2*)(src + (size_t)s_ia[n1] * W64) + 2 * q;
    const ulonglong2* __restrict__ b1p =
        (const ulonglong2*)(src + (size_t)s_ib[n1] * W64) + 2 * q;

    ulonglong2 a00 = a0p[0], a01 = a0p[1];
    ulonglong2 b00 = b0p[0], b01 = b0p[1];
    ulonglong2 a10 = a1p[0], a11 = a1p[1];
    ulonglong2 b10 = b1p[0], b11 = b1p[1];

    uint64_t ma0 = s_m[0][n0], mb0 = s_m[1][n0];
    uint64_t ma1 = s_m[0][n1], mb1 = s_m[1][n1];

    ulonglong2 r;
    ulonglong2* __restrict__ d0 = (ulonglong2*)(dst + (size_t)(nb + n0) * W64) + 2 * q;
    ulonglong2* __restrict__ d1 = (ulonglong2*)(dst + (size_t)(nb + n1) * W64) + 2 * q;

    r.x = (a00.x ^ ma0) & (b00.x ^ mb0);
    r.y = (a00.y ^ ma0) & (b00.y ^ mb0);
    d0[0] = r;
    r.x = (a01.x ^ ma0) & (b01.x ^ mb0);
    r.y = (a01.y ^ ma0) & (b01.y ^ mb0);
    d0[1] = r;
    r.x = (a10.x ^ ma1) & (b10.x ^ mb1);
    r.y = (a10.y ^ ma1) & (b10.y ^ mb1);
    d1[0] = r;
    r.x = (a11.x ^ ma1) & (b11.x ^ mb1);
    r.y = (a11.y ^ ma1) & (b11.y ^ mb1);
    d1[1] = r;
}

// ---------------------------------------------------------------------------
// reduce_k: block per (class, word). 8 warps x 200 neurons; lane l counts
// bits l and l+32 of each broadcast u64; partials combined through smem;
// 64 threads store out[b][c] directly (each output written exactly once,
// so no pre-zero and no atomics).
// ---------------------------------------------------------------------------
__global__ void reduce_k(float* __restrict__ out) {
    __shared__ int sm[8][64];
    int c = blockIdx.x / W64;
    int w = blockIdx.x - c * W64;
    int wj = threadIdx.x >> 5;
    int lane = threadIdx.x & 31;
    const uint64_t* __restrict__ hp =
        g_h[0] + ((size_t)c * GROUP + (size_t)wj * (GROUP / 8)) * W64 + w;
    int c0 = 0, c1 = 0;
#pragma unroll 8
    for (int n = 0; n < GROUP / 8; n++) {
        uint64_t v = hp[(size_t)n * W64];
        c0 += (int)((v >> lane) & 1ULL);
        c1 += (int)((v >> (lane + 32)) & 1ULL);
    }
    sm[wj][lane] = c0;
    sm[wj][lane + 32] = c1;
    __syncthreads();
    int t = threadIdx.x;
    if (t < 64) {
        int s = 0;
#pragma unroll
        for (int j = 0; j < 8; j++) s += sm[j][t];
        int b = w * 64 + t;
        out[(size_t)b * NCLS + c] = (float)s;
    }
}

// ---------------------------------------------------------------------------
// Bind inputs BY ELEMENT COUNT (robust to metadata ordering):
//   x: 3,211,264   idx_a0/idx_b0: 16,000 (a first)   neg0: 32,000
//   idx_a/idx_b: 64,000 (a first)   neg: 128,000
// Output: float32 [BATCH, NCLS]
// ---------------------------------------------------------------------------
extern "C" void kernel_launch(void* const* d_in, const int* in_sizes, int n_in,
                              void* d_out, int out_size) {
    const void* x = nullptr;
    const int *ia0 = nullptr, *ib0 = nullptr, *iah = nullptr, *ibh = nullptr;
    const void *ng0 = nullptr, *ngh = nullptr;

    for (int i = 0; i < n_in; i++) {
        int sz = in_sizes[i];
        if (sz == BATCHN * NI) {
            x = d_in[i];
        } else if (sz == WID) {
            if (!ia0) ia0 = (const int*)d_in[i]; else ib0 = (const int*)d_in[i];
        } else if (sz == WID * 2) {
            ng0 = d_in[i];
        } else if (sz == NHID * WID) {
            if (!iah) iah = (const int*)d_in[i]; else ibh = (const int*)d_in[i];
        } else if (sz == NHID * WID * 2) {
            ngh = d_in[i];
        }
    }
    float* out = (float*)d_out;

    dim3 pg(W64, (NI + 63) / 64);
    pack_x_k<<<pg, 256>>>(x);

    const int LB = WID / NPB;           // 500 blocks, exact
    // input layer: src = g_xp (sel 0), dst = g_h[0] (sel 1)
    layer_k<<<LB, 256>>>(0, 1, ia0, ib0, ng0, 0);

    // 4 hidden layers, ping-pong: h0->h1->h0->h1->h0 (final in g_h[0])
    for (int k = 0; k < NHID; k++) {
        layer_k<<<LB, 256>>>(
            1 + (k & 1), 1 + ((k & 1) ^ 1),
            iah + (size_t)k * WID,
            ibh + (size_t)k * WID,
            ngh, (size_t)k * WID * 2);
    }

    reduce_k<<<NCLS * W64, 256>>>(out);
}

// round 8
// speedup vs baseline: 1.3822x; 1.3822x over previous
#include <cuda_runtime.h>
#include <cstdint>

#define BATCHN 4096
#define NI 784
#define WID 16000
#define NHID 4
#define NLAYERS 5                // input layer + 4 hidden
#define NCLS 10
#define W64 (BATCHN / 64)        // 64
#define NSLICE (BATCHN / 32)     // 128 CTA slices of 32 samples
#define GROUP (WID / NCLS)       // 1600 neurons per class

// Device-resident state; referenced ONLY from device code.
__device__ uint64_t g_xp[(size_t)NI * W64];         // packed input, 401 KB
__device__ uint32_t g_gidx[NLAYERS][WID];           // packed gate descriptors
__device__ uint32_t g_ht[NSLICE][WID];              // final layer, transposed
__device__ int g_mode;

static __device__ __forceinline__ uint32_t read_bool(const void* __restrict__ p,
                                                     size_t e, int mode) {
    if (mode == 1) return ((const uint32_t*)p)[e] != 0u;
    if (mode == 0) return ((const uint8_t*)p)[e] != 0u;
    return ((const uint16_t*)p)[e] != 0u;
}

static __device__ __forceinline__ int detect_mode(const uint32_t* __restrict__ x) {
    bool w32 = true, bf16 = true, u8 = true;
    for (int i = 0; i < 64; i++) {
        uint32_t w = x[i];
        if (!(w == 0u || w == 1u || w == 0x3F800000u)) w32 = false;
        uint32_t h0 = w & 0xFFFFu, h1 = w >> 16;
        if (!((h0 == 0u || h0 == 0x3F80u) && (h1 == 0u || h1 == 0x3F80u))) bf16 = false;
        if ((w & 0xFEFEFEFEu) != 0u) u8 = false;
    }
    return w32 ? 1 : (bf16 ? 2 : (u8 ? 0 : 1));
}

// ---------------------------------------------------------------------------
// pack_x_k: tiled transpose; coalesced x reads; also publishes g_mode.
// ---------------------------------------------------------------------------
__global__ void pack_x_k(const void* __restrict__ x) {
    __shared__ uint8_t tile[64][65];
    __shared__ int s_mode;
    if (threadIdx.x == 0) {
        int m = detect_mode((const uint32_t*)x);
        s_mode = m;
        g_mode = m;              // same value from every block: race-free
    }
    __syncthreads();
    int mode = s_mode;
    int w = blockIdx.x;
    int i0 = blockIdx.y * 64;
    int tx = threadIdx.x & 63;
    int ty = threadIdx.x >> 6;
#pragma unroll
    for (int r = 0; r < 16; r++) {
        int j = r * 4 + ty;
        int i = i0 + tx;
        uint8_t v = 0;
        if (i < NI) v = (uint8_t)read_bool(x, (size_t)(w * 64 + j) * NI + i, mode);
        tile[j][tx] = v;
    }
    __syncthreads();
    if (threadIdx.x < 64) {
        int i = i0 + (int)threadIdx.x;
        if (i < NI) {
            uint64_t acc = 0;
#pragma unroll
            for (int j = 0; j < 64; j++)
                acc |= (uint64_t)tile[j][threadIdx.x] << j;
            g_xp[(size_t)i * W64 + w] = acc;
        }
    }
}

// ---------------------------------------------------------------------------
// prep_idx_k: pack (ia, ib, na, nb) -> one u32 per gate, all 5 layers.
// ia/ib < 16384 -> 14 bits each; negation flags in bits 28/29.
// ---------------------------------------------------------------------------
__global__ void prep_idx_k(const int* __restrict__ ia0, const int* __restrict__ ib0,
                           const void* __restrict__ ng0,
                           const int* __restrict__ iah, const int* __restrict__ ibh,
                           const void* __restrict__ ngh) {
    int t = blockIdx.x * blockDim.x + threadIdx.x;
    if (t >= NLAYERS * WID) return;
    int layer = t / WID;
    int n = t - layer * WID;
    int mode = g_mode;
    uint32_t ia, ib, na, nb;
    if (layer == 0) {
        ia = (uint32_t)ia0[n];
        ib = (uint32_t)ib0[n];
        na = read_bool(ng0, 2 * (size_t)n, mode);
        nb = read_bool(ng0, 2 * (size_t)n + 1, mode);
    } else {
        int k = layer - 1;
        ia = (uint32_t)iah[(size_t)k * WID + n];
        ib = (uint32_t)ibh[(size_t)k * WID + n];
        na = read_bool(ngh, ((size_t)k * WID + n) * 2, mode);
        nb = read_bool(ngh, ((size_t)k * WID + n) * 2 + 1, mode);
    }
    g_gidx[layer][n] = ia | (ib << 14) | (na << 28) | (nb << 29);
}

// ---------------------------------------------------------------------------
// fused_k: CTA = one 32-sample batch slice. Entire 16000-wide activation
// lives in smem (double-buffered u32); all 5 layers run with LDS gathers.
// Final layer streams coalesced to g_ht[slice][neuron].
// ---------------------------------------------------------------------------
#define SM_BUF 16384
#define SM_WORDS (2 * SM_BUF + NI)
#define SM_BYTES (SM_WORDS * 4)

__global__ void __launch_bounds__(1024) fused_k() {
    extern __shared__ uint32_t sm[];
    uint32_t* h0 = sm;
    uint32_t* h1 = sm + SM_BUF;
    uint32_t* xp = sm + 2 * SM_BUF;

    int s = blockIdx.x;              // slice 0..127 -> samples [32s, 32s+32)
    int t = threadIdx.x;
    int w = s >> 1;
    int half = (s & 1) * 32;

    for (int i = t; i < NI; i += 1024)
        xp[i] = (uint32_t)(g_xp[(size_t)i * W64 + w] >> half);
    __syncthreads();

    // Layer 0: xp -> h0
    {
        const uint32_t* __restrict__ gl = g_gidx[0];
#pragma unroll 4
        for (int g = t; g < WID; g += 1024) {
            uint32_t d = gl[g];
            uint32_t a = xp[d & 0x3FFFu];
            uint32_t b = xp[(d >> 14) & 0x3FFFu];
            h0[g] = (a ^ (0u - ((d >> 28) & 1u))) & (b ^ (0u - ((d >> 29) & 1u)));
        }
    }
    __syncthreads();

    // Hidden layers 1..4; last one writes to gmem (transposed layout).
#pragma unroll
    for (int L = 1; L < NLAYERS; L++) {
        const uint32_t* __restrict__ hs = ((L & 1) == 1) ? h0 : h1;
        const uint32_t* __restrict__ gl = g_gidx[L];
        if (L == NLAYERS - 1) {
            uint32_t* __restrict__ go = g_ht[s];
#pragma unroll 4
            for (int g = t; g < WID; g += 1024) {
                uint32_t d = gl[g];
                uint32_t a = hs[d & 0x3FFFu];
                uint32_t b = hs[(d >> 14) & 0x3FFFu];
                go[g] = (a ^ (0u - ((d >> 28) & 1u))) & (b ^ (0u - ((d >> 29) & 1u)));
            }
        } else {
            uint32_t* __restrict__ hd = ((L & 1) == 1) ? h1 : h0;
#pragma unroll 4
            for (int g = t; g < WID; g += 1024) {
                uint32_t d = gl[g];
                uint32_t a = hs[d & 0x3FFFu];
                uint32_t b = hs[(d >> 14) & 0x3FFFu];
                hd[g] = (a ^ (0u - ((d >> 28) & 1u))) & (b ^ (0u - ((d >> 29) & 1u)));
            }
            __syncthreads();
        }
    }
}

// ---------------------------------------------------------------------------
// reduce_k: warp per (class, slice). Lanes CSA-accumulate 50 coalesced u32
// words (1600 neurons) into 6 bit-planes; ballot+popc transposes lanes->bits.
// Every output written exactly once; no atomics, no pre-zero.
// ---------------------------------------------------------------------------
__global__ void reduce_k(float* __restrict__ out) {
    int gw = (blockIdx.x * blockDim.x + threadIdx.x) >> 5;
    int lane = threadIdx.x & 31;
    if (gw >= NCLS * NSLICE) return;
    int c = gw / NSLICE;
    int s = gw - c * NSLICE;
    const uint32_t* __restrict__ p = g_ht[s] + (size_t)c * GROUP + lane;

    uint32_t s0 = 0, s1 = 0, s2 = 0, s3 = 0, s4 = 0, s5 = 0;
#pragma unroll
    for (int k = 0; k < GROUP / 32; k++) {       // 50 words per lane
        uint32_t cc = p[(size_t)k * 32];
        uint32_t tt;
        tt = s0 & cc; s0 ^= cc; cc = tt;
        tt = s1 & cc; s1 ^= cc; cc = tt;
        tt = s2 & cc; s2 ^= cc; cc = tt;
        tt = s3 & cc; s3 ^= cc; cc = tt;
        tt = s4 & cc; s4 ^= cc; cc = tt;
        s5 ^= cc;                                 // count <= 50 < 64: no carry out
    }
#pragma unroll
    for (int b = 0; b < 32; b++) {
        int tot = __popc(__ballot_sync(0xFFFFFFFFu, (s0 >> b) & 1u))
                + 2  * __popc(__ballot_sync(0xFFFFFFFFu, (s1 >> b) & 1u))
                + 4  * __popc(__ballot_sync(0xFFFFFFFFu, (s2 >> b) & 1u))
                + 8  * __popc(__ballot_sync(0xFFFFFFFFu, (s3 >> b) & 1u))
                + 16 * __popc(__ballot_sync(0xFFFFFFFFu, (s4 >> b) & 1u))
                + 32 * __popc(__ballot_sync(0xFFFFFFFFu, (s5 >> b) & 1u));
        if (lane == b)
            out[(size_t)(s * 32 + b) * NCLS + c] = (float)tot;
    }
}

// ---------------------------------------------------------------------------
// Bind inputs BY ELEMENT COUNT (robust to metadata ordering).
// Output: float32 [BATCH, NCLS]
// ---------------------------------------------------------------------------
extern "C" void kernel_launch(void* const* d_in, const int* in_sizes, int n_in,
                              void* d_out, int out_size) {
    const void* x = nullptr;
    const int *ia0 = nullptr, *ib0 = nullptr, *iah = nullptr, *ibh = nullptr;
    const void *ng0 = nullptr, *ngh = nullptr;

    for (int i = 0; i < n_in; i++) {
        int sz = in_sizes[i];
        if (sz == BATCHN * NI) {
            x = d_in[i];
        } else if (sz == WID) {
            if (!ia0) ia0 = (const int*)d_in[i]; else ib0 = (const int*)d_in[i];
        } else if (sz == WID * 2) {
            ng0 = d_in[i];
        } else if (sz == NHID * WID) {
            if (!iah) iah = (const int*)d_in[i]; else ibh = (const int*)d_in[i];
        } else if (sz == NHID * WID * 2) {
            ngh = d_in[i];
        }
    }
    float* out = (float*)d_out;

    static bool attr_set = false;
    if (!attr_set) {
        cudaFuncSetAttribute(fused_k, cudaFuncAttributeMaxDynamicSharedMemorySize,
                             SM_BYTES);
        attr_set = true;
    }

    dim3 pg(W64, (NI + 63) / 64);
    pack_x_k<<<pg, 256>>>(x);

    prep_idx_k<<<(NLAYERS * WID + 255) / 256, 256>>>(ia0, ib0, ng0, iah, ibh, ngh);

    fused_k<<<NSLICE, 1024, SM_BYTES>>>();

    reduce_k<<<(NCLS * NSLICE * 32 + 255) / 256, 256>>>(out);
}

// round 9
// speedup vs baseline: 1.5635x; 1.1311x over previous
#include <cuda_runtime.h>
#include <cstdint>

#define BATCHN 4096
#define NI 784
#define WID 16000
#define NHID 4
#define NLAYERS 5                // input layer + 4 hidden
#define NCLS 10
#define W64 (BATCHN / 64)        // 64
#define NSLICE (BATCHN / 32)     // 128 CTA slices of 32 samples
#define GROUP (WID / NCLS)       // 1600 neurons per class
#define HGRP (GROUP / 2)         // 800 words per reduce warp
#define KWORDS (HGRP / 32)       // 25 words per lane

// Device-resident state; referenced ONLY from device code.
__device__ uint64_t g_xp[(size_t)NI * W64];         // packed input, 401 KB
__device__ uint32_t g_gidx[NLAYERS][WID];           // packed gate descriptors
__device__ int g_mode;

static __device__ __forceinline__ uint32_t read_bool(const void* __restrict__ p,
                                                     size_t e, int mode) {
    if (mode == 1) return ((const uint32_t*)p)[e] != 0u;
    if (mode == 0) return ((const uint8_t*)p)[e] != 0u;
    return ((const uint16_t*)p)[e] != 0u;
}

static __device__ __forceinline__ int detect_mode(const uint32_t* __restrict__ x) {
    bool w32 = true, bf16 = true, u8 = true;
    for (int i = 0; i < 64; i++) {
        uint32_t w = x[i];
        if (!(w == 0u || w == 1u || w == 0x3F800000u)) w32 = false;
        uint32_t h0 = w & 0xFFFFu, h1 = w >> 16;
        if (!((h0 == 0u || h0 == 0x3F80u) && (h1 == 0u || h1 == 0x3F80u))) bf16 = false;
        if ((w & 0xFEFEFEFEu) != 0u) u8 = false;
    }
    return w32 ? 1 : (bf16 ? 2 : (u8 ? 0 : 1));
}

// ---------------------------------------------------------------------------
// pack_x_k: tiled transpose; coalesced x reads; also publishes g_mode.
// ---------------------------------------------------------------------------
__global__ void pack_x_k(const void* __restrict__ x) {
    __shared__ uint8_t tile[64][65];
    __shared__ int s_mode;
    if (threadIdx.x == 0) {
        int m = detect_mode((const uint32_t*)x);
        s_mode = m;
        g_mode = m;              // same value from every block: race-free
    }
    __syncthreads();
    int mode = s_mode;
    int w = blockIdx.x;
    int i0 = blockIdx.y * 64;
    int tx = threadIdx.x & 63;
    int ty = threadIdx.x >> 6;
#pragma unroll
    for (int r = 0; r < 16; r++) {
        int j = r * 4 + ty;
        int i = i0 + tx;
        uint8_t v = 0;
        if (i < NI) v = (uint8_t)read_bool(x, (size_t)(w * 64 + j) * NI + i, mode);
        tile[j][tx] = v;
    }
    __syncthreads();
    if (threadIdx.x < 64) {
        int i = i0 + (int)threadIdx.x;
        if (i < NI) {
            uint64_t acc = 0;
#pragma unroll
            for (int j = 0; j < 64; j++)
                acc |= (uint64_t)tile[j][threadIdx.x] << j;
            g_xp[(size_t)i * W64 + w] = acc;
        }
    }
}

// ---------------------------------------------------------------------------
// prep_idx_k: pack (ia, ib, na, nb) -> one u32 per gate, all 5 layers.
// ---------------------------------------------------------------------------
__global__ void prep_idx_k(const int* __restrict__ ia0, const int* __restrict__ ib0,
                           const void* __restrict__ ng0,
                           const int* __restrict__ iah, const int* __restrict__ ibh,
                           const void* __restrict__ ngh) {
    int t = blockIdx.x * blockDim.x + threadIdx.x;
    if (t >= NLAYERS * WID) return;
    int layer = t / WID;
    int n = t - layer * WID;
    int mode = g_mode;
    uint32_t ia, ib, na, nb;
    if (layer == 0) {
        ia = (uint32_t)ia0[n];
        ib = (uint32_t)ib0[n];
        na = read_bool(ng0, 2 * (size_t)n, mode);
        nb = read_bool(ng0, 2 * (size_t)n + 1, mode);
    } else {
        int k = layer - 1;
        ia = (uint32_t)iah[(size_t)k * WID + n];
        ib = (uint32_t)ibh[(size_t)k * WID + n];
        na = read_bool(ngh, ((size_t)k * WID + n) * 2, mode);
        nb = read_bool(ngh, ((size_t)k * WID + n) * 2 + 1, mode);
    }
    g_gidx[layer][n] = ia | (ib << 14) | (na << 28) | (nb << 29);
}

// ---------------------------------------------------------------------------
// fused_k: CTA = one 32-sample batch slice. Entire 16000-wide activation in
// smem (double-buffered u32); all 5 layers via LDS gathers; then the GroupSum
// is computed in-CTA (20 warps, 2 per class, CSA bit-planes + ballots) and
// stored straight to out. No intermediate gmem traffic at all.
// ---------------------------------------------------------------------------
#define SM_BUF 16384
#define SM_WORDS (2 * SM_BUF + NI)
#define SM_BYTES (SM_WORDS * 4)

__global__ void __launch_bounds__(1024) fused_k(float* __restrict__ out) {
    extern __shared__ uint32_t sm[];
    uint32_t* h0 = sm;
    uint32_t* h1 = sm + SM_BUF;
    uint32_t* xp = sm + 2 * SM_BUF;
    __shared__ int partial[NCLS][2][32];

    int s = blockIdx.x;              // slice 0..127 -> samples [32s, 32s+32)
    int t = threadIdx.x;
    int w = s >> 1;
    int half = (s & 1) * 32;

    for (int i = t; i < NI; i += 1024)
        xp[i] = (uint32_t)(g_xp[(size_t)i * W64 + w] >> half);
    __syncthreads();

    // Layer 0: xp -> h0
    {
        const uint32_t* __restrict__ gl = g_gidx[0];
#pragma unroll 4
        for (int g = t; g < WID; g += 1024) {
            uint32_t d = gl[g];
            uint32_t a = xp[d & 0x3FFFu];
            uint32_t b = xp[(d >> 14) & 0x3FFFu];
            h0[g] = (a ^ (0u - ((d >> 28) & 1u))) & (b ^ (0u - ((d >> 29) & 1u)));
        }
    }
    __syncthreads();

    // Hidden layers 1..4: h0->h1->h0->h1->h0 (final activations in h0)
#pragma unroll
    for (int L = 1; L < NLAYERS; L++) {
        const uint32_t* __restrict__ hs = ((L & 1) == 1) ? h0 : h1;
        uint32_t* __restrict__ hd = ((L & 1) == 1) ? h1 : h0;
        const uint32_t* __restrict__ gl = g_gidx[L];
#pragma unroll 4
        for (int g = t; g < WID; g += 1024) {
            uint32_t d = gl[g];
            uint32_t a = hs[d & 0x3FFFu];
            uint32_t b = hs[(d >> 14) & 0x3FFFu];
            hd[g] = (a ^ (0u - ((d >> 28) & 1u))) & (b ^ (0u - ((d >> 29) & 1u)));
        }
        __syncthreads();
    }

    // In-CTA GroupSum from h0. 20 warps: warp = (class c, half hf).
    int wid = t >> 5;
    int lane = t & 31;
    if (wid < 2 * NCLS) {
        int c = wid >> 1;
        int hf = wid & 1;
        const uint32_t* __restrict__ p = h0 + c * GROUP + hf * HGRP + lane;
        uint32_t s0 = 0, s1 = 0, s2 = 0, s3 = 0, s4 = 0;
#pragma unroll
        for (int k = 0; k < KWORDS; k++) {       // 25 stride-1 LDS words
            uint32_t cc = p[k * 32];
            uint32_t tt;
            tt = s0 & cc; s0 ^= cc; cc = tt;
            tt = s1 & cc; s1 ^= cc; cc = tt;
            tt = s2 & cc; s2 ^= cc; cc = tt;
            tt = s3 & cc; s3 ^= cc; cc = tt;
            s4 ^= cc;                             // counts <= 25 < 32
        }
#pragma unroll
        for (int b = 0; b < 32; b++) {
            int tot = __popc(__ballot_sync(0xFFFFFFFFu, (s0 >> b) & 1u))
                    + 2  * __popc(__ballot_sync(0xFFFFFFFFu, (s1 >> b) & 1u))
                    + 4  * __popc(__ballot_sync(0xFFFFFFFFu, (s2 >> b) & 1u))
                    + 8  * __popc(__ballot_sync(0xFFFFFFFFu, (s3 >> b) & 1u))
                    + 16 * __popc(__ballot_sync(0xFFFFFFFFu, (s4 >> b) & 1u));
            if (lane == b) partial[c][hf][b] = tot;
        }
    }
    __syncthreads();

    // 320 threads: combine halves, store exactly once.
    if (t < NCLS * 32) {
        int c = t >> 5;
        int b = t & 31;
        out[(size_t)(s * 32 + b) * NCLS + c] =
            (float)(partial[c][0][b] + partial[c][1][b]);
    }
}

// ---------------------------------------------------------------------------
// Bind inputs BY ELEMENT COUNT (robust to metadata ordering).
// Output: float32 [BATCH, NCLS]
// ---------------------------------------------------------------------------
extern "C" void kernel_launch(void* const* d_in, const int* in_sizes, int n_in,
                              void* d_out, int out_size) {
    const void* x = nullptr;
    const int *ia0 = nullptr, *ib0 = nullptr, *iah = nullptr, *ibh = nullptr;
    const void *ng0 = nullptr, *ngh = nullptr;

    for (int i = 0; i < n_in; i++) {
        int sz = in_sizes[i];
        if (sz == BATCHN * NI) {
            x = d_in[i];
        } else if (sz == WID) {
            if (!ia0) ia0 = (const int*)d_in[i]; else ib0 = (const int*)d_in[i];
        } else if (sz == WID * 2) {
            ng0 = d_in[i];
        } else if (sz == NHID * WID) {
            if (!iah) iah = (const int*)d_in[i]; else ibh = (const int*)d_in[i];
        } else if (sz == NHID * WID * 2) {
            ngh = d_in[i];
        }
    }
    float* out = (float*)d_out;

    static bool attr_set = false;
    if (!attr_set) {
        cudaFuncSetAttribute(fused_k, cudaFuncAttributeMaxDynamicSharedMemorySize,
                             SM_BYTES);
        attr_set = true;
    }

    dim3 pg(W64, (NI + 63) / 64);
    pack_x_k<<<pg, 256>>>(x);

    prep_idx_k<<<(NLAYERS * WID + 255) / 256, 256>>>(ia0, ib0, ng0, iah, ibh, ngh);

    fused_k<<<NSLICE, 1024, SM_BYTES>>>(out);
}